// round 1
// baseline (speedup 1.0000x reference)
#include <cuda_runtime.h>

#define N_USERS 200000
#define N_ITEMS 100000
#define N_NODES (N_USERS + N_ITEMS)
#define DIM 64
#define EPS 1e-12f

// ---------------------------------------------------------------------------
// Kernel 1: zero the accumulator (d_out is poisoned by the harness)
// ---------------------------------------------------------------------------
__global__ void zero_kernel(float4* __restrict__ out, int n4) {
    int i = blockIdx.x * blockDim.x + threadIdx.x;
    if (i < n4) out[i] = make_float4(0.f, 0.f, 0.f, 0.f);
}

// ---------------------------------------------------------------------------
// Kernel 2: edge-parallel weighted scatter-add.
// 16 threads per edge, each owns one float4 (4 dims) of the 64-dim row.
// Gather h[src] (user or item table), scale by w, atomicAdd into out[dst].
// ---------------------------------------------------------------------------
__global__ void scatter_kernel(const float* __restrict__ ue,
                               const float* __restrict__ ie,
                               const int*   __restrict__ src,
                               const int*   __restrict__ dst,
                               const float* __restrict__ w,
                               float*       __restrict__ out,
                               int n_edges) {
    long long gid = (long long)blockIdx.x * blockDim.x + threadIdx.x;
    int e = (int)(gid >> 4);
    int c = (int)(gid & 15);
    if (e >= n_edges) return;

    int   s  = __ldg(src + e);
    int   d  = __ldg(dst + e);
    float wt = __ldg(w + e);

    const float* hp = (s < N_USERS)
        ? (ue + (long long)s * DIM)
        : (ie + (long long)(s - N_USERS) * DIM);

    float4 v = __ldg(((const float4*)hp) + c);
    v.x *= wt; v.y *= wt; v.z *= wt; v.w *= wt;

    atomicAdd(((float4*)(out + (long long)d * DIM)) + c, v);
}

// ---------------------------------------------------------------------------
// Kernel 3: in-place row L2 normalize. One warp per node, float2 per lane.
// ---------------------------------------------------------------------------
__global__ void normalize_kernel(float* __restrict__ out, int n_nodes) {
    int gid  = blockIdx.x * blockDim.x + threadIdx.x;
    int node = gid >> 5;
    int lane = gid & 31;
    if (node >= n_nodes) return;

    float2* row = (float2*)(out + (long long)node * DIM);
    float2  v   = row[lane];
    float   ss  = v.x * v.x + v.y * v.y;

    #pragma unroll
    for (int off = 16; off; off >>= 1)
        ss += __shfl_xor_sync(0xffffffffu, ss, off);

    float norm  = sqrtf(ss);
    float scale = 1.0f / fmaxf(norm, EPS);
    v.x *= scale;
    v.y *= scale;
    row[lane] = v;
}

// ---------------------------------------------------------------------------
// Launch
// inputs (metadata order): user_embedding [200000*64] f32,
//                          item_embedding [100000*64] f32,
//                          src [1250000] i32, dst [1250000] i32,
//                          edge_weight [1250000] f32
// output: [300000*64] f32
// ---------------------------------------------------------------------------
extern "C" void kernel_launch(void* const* d_in, const int* in_sizes, int n_in,
                              void* d_out, int out_size) {
    const float* ue  = (const float*)d_in[0];
    const float* ie  = (const float*)d_in[1];
    const int*   src = (const int*)  d_in[2];
    const int*   dst = (const int*)  d_in[3];
    const float* w   = (const float*)d_in[4];
    float*       out = (float*)d_out;

    const int n_edges = in_sizes[2];

    // 1) zero accumulator
    int n4 = N_NODES * DIM / 4;  // 4.8M float4
    zero_kernel<<<(n4 + 255) / 256, 256>>>((float4*)out, n4);

    // 2) scatter-add
    long long total = (long long)n_edges * 16;
    int blocks = (int)((total + 255) / 256);
    scatter_kernel<<<blocks, 256>>>(ue, ie, src, dst, w, out, n_edges);

    // 3) normalize
    long long nt = (long long)N_NODES * 32;
    normalize_kernel<<<(int)((nt + 255) / 256), 256>>>(out, N_NODES);
}

// round 2
// speedup vs baseline: 1.0849x; 1.0849x over previous
#include <cuda_runtime.h>

#define N_USERS 200000
#define N_ITEMS 100000
#define N_NODES (N_USERS + N_ITEMS)
#define N_EDGES_MAX 1250000
#define DIM 64
#define EPS 1e-12f

#define SCAN_CHUNK 1024
#define NSB ((N_NODES + SCAN_CHUNK - 1) / SCAN_CHUNK)  // 293

// ---------------------------------------------------------------------------
// Scratch (device globals — no allocations allowed)
// ---------------------------------------------------------------------------
__device__ int g_counts[N_NODES];
__device__ int g_offsets[N_NODES + 1];
__device__ int g_cursor[N_NODES];
__device__ int g_blockSums[NSB];
__device__ int g_sorted[N_EDGES_MAX];

// ---------------------------------------------------------------------------
// 1) zero histogram counters
// ---------------------------------------------------------------------------
__global__ void zero_counts_kernel() {
    int i = blockIdx.x * blockDim.x + threadIdx.x;
    if (i < N_NODES) g_counts[i] = 0;
}

// ---------------------------------------------------------------------------
// 2) histogram of dst
// ---------------------------------------------------------------------------
__global__ void hist_kernel(const int* __restrict__ dst, int n_edges) {
    int e = blockIdx.x * blockDim.x + threadIdx.x;
    if (e < n_edges) atomicAdd(&g_counts[dst[e]], 1);
}

// ---------------------------------------------------------------------------
// 3a) per-block exclusive scan (1024 elems / block, 256 threads x 4)
//     local exclusive prefixes -> g_offsets, block totals -> g_blockSums
// ---------------------------------------------------------------------------
__global__ void scan1_kernel() {
    __shared__ int warpTot[8];
    int b = blockIdx.x, t = threadIdx.x;
    int base = b * SCAN_CHUNK + t * 4;

    int v0 = (base + 0 < N_NODES) ? g_counts[base + 0] : 0;
    int v1 = (base + 1 < N_NODES) ? g_counts[base + 1] : 0;
    int v2 = (base + 2 < N_NODES) ? g_counts[base + 2] : 0;
    int v3 = (base + 3 < N_NODES) ? g_counts[base + 3] : 0;
    int s = v0 + v1 + v2 + v3;

    int lane = t & 31, wid = t >> 5;
    int inc = s;
    #pragma unroll
    for (int o = 1; o < 32; o <<= 1) {
        int x = __shfl_up_sync(0xffffffffu, inc, o);
        if (lane >= o) inc += x;
    }
    if (lane == 31) warpTot[wid] = inc;
    __syncthreads();
    if (wid == 0) {
        int wv = (lane < 8) ? warpTot[lane] : 0;
        #pragma unroll
        for (int o = 1; o < 8; o <<= 1) {
            int x = __shfl_up_sync(0xffffffffu, wv, o);
            if (lane >= o) wv += x;
        }
        if (lane < 8) warpTot[lane] = wv;  // inclusive warp totals
    }
    __syncthreads();

    int warpOff = (wid > 0) ? warpTot[wid - 1] : 0;
    int ex = warpOff + inc - s;  // exclusive prefix of this thread

    if (base + 0 < N_NODES) g_offsets[base + 0] = ex;
    if (base + 1 < N_NODES) g_offsets[base + 1] = ex + v0;
    if (base + 2 < N_NODES) g_offsets[base + 2] = ex + v0 + v1;
    if (base + 3 < N_NODES) g_offsets[base + 3] = ex + v0 + v1 + v2;
    if (t == 0) g_blockSums[b] = warpTot[7];
}

// ---------------------------------------------------------------------------
// 3b) scan block sums (single block, NSB <= 1024)
// ---------------------------------------------------------------------------
__global__ void scan2_kernel() {
    __shared__ int sm[1024];
    int t = threadIdx.x;
    int v = (t < NSB) ? g_blockSums[t] : 0;
    sm[t] = v;
    __syncthreads();
    for (int o = 1; o < 1024; o <<= 1) {
        int x = (t >= o) ? sm[t - o] : 0;
        __syncthreads();
        sm[t] += x;
        __syncthreads();
    }
    if (t < NSB) g_blockSums[t] = sm[t] - v;  // exclusive
}

// ---------------------------------------------------------------------------
// 3c) add block bases; initialize cursor; seal offsets
// ---------------------------------------------------------------------------
__global__ void scan3_kernel(int n_edges) {
    int i = blockIdx.x * blockDim.x + threadIdx.x;
    if (i < N_NODES) {
        int off = g_offsets[i] + g_blockSums[i >> 10];
        g_offsets[i] = off;
        g_cursor[i]  = off;
    }
    if (i == 0) g_offsets[N_NODES] = n_edges;
}

// ---------------------------------------------------------------------------
// 4) scatter edge ids into dst-sorted order
// ---------------------------------------------------------------------------
__global__ void scatter_sort_kernel(const int* __restrict__ dst, int n_edges) {
    int e = blockIdx.x * blockDim.x + threadIdx.x;
    if (e < n_edges) {
        int p = atomicAdd(&g_cursor[dst[e]], 1);
        g_sorted[p] = e;
    }
}

// ---------------------------------------------------------------------------
// 5) warp-per-node gather + aggregate + L2-normalize + store (no atomics)
// ---------------------------------------------------------------------------
__global__ void aggregate_kernel(const float* __restrict__ ue,
                                 const float* __restrict__ ie,
                                 const int*   __restrict__ src,
                                 const float* __restrict__ w,
                                 float*       __restrict__ out) {
    int gid  = blockIdx.x * blockDim.x + threadIdx.x;
    int node = gid >> 5;
    int lane = gid & 31;
    if (node >= N_NODES) return;

    int beg = g_offsets[node];
    int end = g_offsets[node + 1];

    float2 acc = make_float2(0.f, 0.f);

    for (int base = beg; base < end; base += 32) {
        int m = min(32, end - base);
        // warp-wide prefetch of edge metadata (breaks the pointer-chase)
        int   eid = (lane < m) ? g_sorted[base + lane] : 0;
        int   s_l = (lane < m) ? __ldg(src + eid) : 0;
        float w_l = (lane < m) ? __ldg(w + eid) : 0.f;

        for (int j = 0; j < m; ++j) {
            int   s  = __shfl_sync(0xffffffffu, s_l, j);
            float wt = __shfl_sync(0xffffffffu, w_l, j);
            const float* hp = (s < N_USERS)
                ? (ue + (long long)s * DIM)
                : (ie + (long long)(s - N_USERS) * DIM);
            float2 v = __ldg(((const float2*)hp) + lane);
            acc.x = fmaf(wt, v.x, acc.x);
            acc.y = fmaf(wt, v.y, acc.y);
        }
    }

    float ss = acc.x * acc.x + acc.y * acc.y;
    #pragma unroll
    for (int off = 16; off; off >>= 1)
        ss += __shfl_xor_sync(0xffffffffu, ss, off);

    float scale = 1.0f / fmaxf(sqrtf(ss), EPS);
    acc.x *= scale;
    acc.y *= scale;
    ((float2*)(out + (long long)node * DIM))[lane] = acc;
}

// ---------------------------------------------------------------------------
// Launch
// inputs: user_embedding [200000*64] f32, item_embedding [100000*64] f32,
//         src [1250000] i32, dst [1250000] i32, edge_weight [1250000] f32
// output: [300000*64] f32
// ---------------------------------------------------------------------------
extern "C" void kernel_launch(void* const* d_in, const int* in_sizes, int n_in,
                              void* d_out, int out_size) {
    const float* ue  = (const float*)d_in[0];
    const float* ie  = (const float*)d_in[1];
    const int*   src = (const int*)  d_in[2];
    const int*   dst = (const int*)  d_in[3];
    const float* w   = (const float*)d_in[4];
    float*       out = (float*)d_out;

    const int E = in_sizes[2];

    zero_counts_kernel<<<(N_NODES + 255) / 256, 256>>>();
    hist_kernel<<<(E + 255) / 256, 256>>>(dst, E);
    scan1_kernel<<<NSB, 256>>>();
    scan2_kernel<<<1, 1024>>>();
    scan3_kernel<<<(N_NODES + 255) / 256, 256>>>(E);
    scatter_sort_kernel<<<(E + 255) / 256, 256>>>(dst, E);

    long long nt = (long long)N_NODES * 32;
    aggregate_kernel<<<(int)((nt + 255) / 256), 256>>>(ue, ie, src, w, out);
}

// round 3
// speedup vs baseline: 1.1047x; 1.0182x over previous
#include <cuda_runtime.h>

#define N_USERS 200000
#define N_ITEMS 100000
#define N_NODES (N_USERS + N_ITEMS)
#define N_EDGES_MAX 1250000
#define DIM 64
#define EPS 1e-12f

// ---------------------------------------------------------------------------
// Scratch (device globals — no allocations allowed)
// ---------------------------------------------------------------------------
__device__ int  g_counts[N_NODES];
__device__ int  g_offsets[N_NODES];
__device__ int  g_cursor[N_NODES];
__device__ int  g_total;
__device__ int2 g_edges[N_EDGES_MAX];   // {src, weight-bits} in dst-grouped order

// ---------------------------------------------------------------------------
// 1) zero histogram counters + global base counter
// ---------------------------------------------------------------------------
__global__ void zero_counts_kernel() {
    int i = blockIdx.x * blockDim.x + threadIdx.x;
    if (i < N_NODES) g_counts[i] = 0;
    if (i == 0) g_total = 0;
}

// ---------------------------------------------------------------------------
// 2) histogram of dst
// ---------------------------------------------------------------------------
__global__ void hist_kernel(const int* __restrict__ dst, int n_edges) {
    int e = blockIdx.x * blockDim.x + threadIdx.x;
    if (e < n_edges) atomicAdd(&g_counts[dst[e]], 1);
}

// ---------------------------------------------------------------------------
// 3) per-block scan of counts; block base via one global atomicAdd.
//    Segment placement is run-varying, but each node's segment is contiguous
//    and sized exactly g_counts[node] — all the aggregate needs.
// ---------------------------------------------------------------------------
__global__ void base_assign_kernel() {
    __shared__ int warpTot[8];
    __shared__ int blockBase;
    int t = threadIdx.x;
    int i = blockIdx.x * blockDim.x + t;
    int lane = t & 31, wid = t >> 5;

    int c = (i < N_NODES) ? g_counts[i] : 0;

    int inc = c;
    #pragma unroll
    for (int o = 1; o < 32; o <<= 1) {
        int x = __shfl_up_sync(0xffffffffu, inc, o);
        if (lane >= o) inc += x;
    }
    if (lane == 31) warpTot[wid] = inc;
    __syncthreads();
    if (wid == 0) {
        int wv = (lane < 8) ? warpTot[lane] : 0;
        #pragma unroll
        for (int o = 1; o < 8; o <<= 1) {
            int x = __shfl_up_sync(0xffffffffu, wv, o);
            if (lane >= o) wv += x;
        }
        if (lane < 8) warpTot[lane] = wv;   // inclusive warp totals
        if (lane == 7) blockBase = atomicAdd(&g_total, wv);
    }
    __syncthreads();

    int ex = ((wid > 0) ? warpTot[wid - 1] : 0) + inc - c;
    if (i < N_NODES) {
        int off = blockBase + ex;
        g_offsets[i] = off;
        g_cursor[i]  = off;
    }
}

// ---------------------------------------------------------------------------
// 4) scatter packed {src, weight} into dst-grouped order
// ---------------------------------------------------------------------------
__global__ void scatter_pack_kernel(const int*   __restrict__ src,
                                    const int*   __restrict__ dst,
                                    const float* __restrict__ w,
                                    int n_edges) {
    int e = blockIdx.x * blockDim.x + threadIdx.x;
    if (e < n_edges) {
        int p = atomicAdd(&g_cursor[dst[e]], 1);
        g_edges[p] = make_int2(src[e], __float_as_int(w[e]));
    }
}

// ---------------------------------------------------------------------------
// 5) warp-per-node gather + aggregate + L2-normalize + store
// ---------------------------------------------------------------------------
__global__ void aggregate_kernel(const float* __restrict__ ue,
                                 const float* __restrict__ ie,
                                 float*       __restrict__ out) {
    int gid  = blockIdx.x * blockDim.x + threadIdx.x;
    int node = gid >> 5;
    int lane = gid & 31;
    if (node >= N_NODES) return;

    int beg = g_offsets[node];
    int cnt = g_counts[node];
    int end = beg + cnt;

    float accx = 0.f, accy = 0.f;

    for (int base = beg; base < end; base += 32) {
        int m = min(32, end - base);
        // coalesced warp-wide prefetch of packed edge payloads
        int2 ew = (lane < m) ? __ldg(&g_edges[base + lane]) : make_int2(0, 0);

        int j = 0;
        for (; j + 2 <= m; j += 2) {
            int   s0 = __shfl_sync(0xffffffffu, ew.x, j);
            int   w0 = __shfl_sync(0xffffffffu, ew.y, j);
            int   s1 = __shfl_sync(0xffffffffu, ew.x, j + 1);
            int   w1 = __shfl_sync(0xffffffffu, ew.y, j + 1);
            const float* h0 = (s0 < N_USERS) ? (ue + (long long)s0 * DIM)
                                             : (ie + (long long)(s0 - N_USERS) * DIM);
            const float* h1 = (s1 < N_USERS) ? (ue + (long long)s1 * DIM)
                                             : (ie + (long long)(s1 - N_USERS) * DIM);
            float2 v0 = __ldg(((const float2*)h0) + lane);
            float2 v1 = __ldg(((const float2*)h1) + lane);
            float  f0 = __int_as_float(w0);
            float  f1 = __int_as_float(w1);
            accx = fmaf(f0, v0.x, accx);
            accy = fmaf(f0, v0.y, accy);
            accx = fmaf(f1, v1.x, accx);
            accy = fmaf(f1, v1.y, accy);
        }
        if (j < m) {
            int   s0 = __shfl_sync(0xffffffffu, ew.x, j);
            int   w0 = __shfl_sync(0xffffffffu, ew.y, j);
            const float* h0 = (s0 < N_USERS) ? (ue + (long long)s0 * DIM)
                                             : (ie + (long long)(s0 - N_USERS) * DIM);
            float2 v0 = __ldg(((const float2*)h0) + lane);
            float  f0 = __int_as_float(w0);
            accx = fmaf(f0, v0.x, accx);
            accy = fmaf(f0, v0.y, accy);
        }
    }

    float ss = accx * accx + accy * accy;
    #pragma unroll
    for (int off = 16; off; off >>= 1)
        ss += __shfl_xor_sync(0xffffffffu, ss, off);

    float scale = 1.0f / fmaxf(sqrtf(ss), EPS);
    float2 r = make_float2(accx * scale, accy * scale);
    ((float2*)(out + (long long)node * DIM))[lane] = r;
}

// ---------------------------------------------------------------------------
// Launch
// ---------------------------------------------------------------------------
extern "C" void kernel_launch(void* const* d_in, const int* in_sizes, int n_in,
                              void* d_out, int out_size) {
    const float* ue  = (const float*)d_in[0];
    const float* ie  = (const float*)d_in[1];
    const int*   src = (const int*)  d_in[2];
    const int*   dst = (const int*)  d_in[3];
    const float* w   = (const float*)d_in[4];
    float*       out = (float*)d_out;

    const int E = in_sizes[2];

    zero_counts_kernel<<<(N_NODES + 255) / 256, 256>>>();
    hist_kernel<<<(E + 255) / 256, 256>>>(dst, E);
    base_assign_kernel<<<(N_NODES + 255) / 256, 256>>>();
    scatter_pack_kernel<<<(E + 255) / 256, 256>>>(src, dst, w, E);

    long long nt = (long long)N_NODES * 32;
    aggregate_kernel<<<(int)((nt + 255) / 256), 256>>>(ue, ie, out);
}

// round 4
// speedup vs baseline: 1.4637x; 1.3250x over previous
#include <cuda_runtime.h>

#define N_USERS 200000
#define N_ITEMS 100000
#define N_NODES (N_USERS + N_ITEMS)
#define N_EDGES_MAX 1250000
#define DIM 64
#define EPS 1e-12f

// ---------------------------------------------------------------------------
// Scratch (device globals — no allocations allowed)
// ---------------------------------------------------------------------------
__device__ int  g_counts[N_NODES];
__device__ int  g_offsets[N_NODES];
__device__ int  g_cursor[N_NODES];
__device__ int  g_total;
__device__ int2 g_edges[N_EDGES_MAX];   // {src, weight-bits} in dst-grouped order

// ---------------------------------------------------------------------------
// 1) zero histogram counters + global base counter
// ---------------------------------------------------------------------------
__global__ void zero_counts_kernel() {
    int i = blockIdx.x * blockDim.x + threadIdx.x;
    if (i < N_NODES) g_counts[i] = 0;
    if (i == 0) g_total = 0;
}

// ---------------------------------------------------------------------------
// 2) histogram of dst — 4 edges per thread (vector load, fire-and-forget RED)
// ---------------------------------------------------------------------------
__global__ void hist_kernel(const int* __restrict__ dst, int n_edges) {
    int i  = blockIdx.x * blockDim.x + threadIdx.x;
    int e0 = i * 4;
    if (e0 + 3 < n_edges) {
        int4 d = *(const int4*)(dst + e0);
        atomicAdd(&g_counts[d.x], 1);
        atomicAdd(&g_counts[d.y], 1);
        atomicAdd(&g_counts[d.z], 1);
        atomicAdd(&g_counts[d.w], 1);
    } else {
        for (int e = e0; e < n_edges; ++e) atomicAdd(&g_counts[dst[e]], 1);
    }
}

// ---------------------------------------------------------------------------
// 3) per-block scan of counts; block base via one global atomicAdd.
// ---------------------------------------------------------------------------
__global__ void base_assign_kernel() {
    __shared__ int warpTot[8];
    __shared__ int blockBase;
    int t = threadIdx.x;
    int i = blockIdx.x * blockDim.x + t;
    int lane = t & 31, wid = t >> 5;

    int c = (i < N_NODES) ? g_counts[i] : 0;

    int inc = c;
    #pragma unroll
    for (int o = 1; o < 32; o <<= 1) {
        int x = __shfl_up_sync(0xffffffffu, inc, o);
        if (lane >= o) inc += x;
    }
    if (lane == 31) warpTot[wid] = inc;
    __syncthreads();
    if (wid == 0) {
        int wv = (lane < 8) ? warpTot[lane] : 0;
        #pragma unroll
        for (int o = 1; o < 8; o <<= 1) {
            int x = __shfl_up_sync(0xffffffffu, wv, o);
            if (lane >= o) wv += x;
        }
        if (lane < 8) warpTot[lane] = wv;   // inclusive warp totals
        if (lane == 7) blockBase = atomicAdd(&g_total, wv);
    }
    __syncthreads();

    int ex = ((wid > 0) ? warpTot[wid - 1] : 0) + inc - c;
    if (i < N_NODES) {
        int off = blockBase + ex;
        g_offsets[i] = off;
        g_cursor[i]  = off;
    }
}

// ---------------------------------------------------------------------------
// 4) scatter packed {src, weight} — 4 edges/thread for MLP on atomic returns
// ---------------------------------------------------------------------------
__global__ void scatter_pack_kernel(const int*   __restrict__ src,
                                    const int*   __restrict__ dst,
                                    const float* __restrict__ w,
                                    int n_edges) {
    int i  = blockIdx.x * blockDim.x + threadIdx.x;
    int e0 = i * 4;
    if (e0 + 3 < n_edges) {
        int4   s  = *(const int4*)  (src + e0);
        int4   d  = *(const int4*)  (dst + e0);
        float4 ww = *(const float4*)(w   + e0);
        int p0 = atomicAdd(&g_cursor[d.x], 1);
        int p1 = atomicAdd(&g_cursor[d.y], 1);
        int p2 = atomicAdd(&g_cursor[d.z], 1);
        int p3 = atomicAdd(&g_cursor[d.w], 1);
        g_edges[p0] = make_int2(s.x, __float_as_int(ww.x));
        g_edges[p1] = make_int2(s.y, __float_as_int(ww.y));
        g_edges[p2] = make_int2(s.z, __float_as_int(ww.z));
        g_edges[p3] = make_int2(s.w, __float_as_int(ww.w));
    } else {
        for (int e = e0; e < n_edges; ++e) {
            int p = atomicAdd(&g_cursor[dst[e]], 1);
            g_edges[p] = make_int2(src[e], __float_as_int(w[e]));
        }
    }
}

// ---------------------------------------------------------------------------
// 5) HALF-WARP (16 lanes, float4) per node: gather + aggregate + normalize.
//    2 independent node chains per warp -> halves exposed latency.
// ---------------------------------------------------------------------------
__global__ void aggregate_kernel(const float* __restrict__ ue,
                                 const float* __restrict__ ie,
                                 float*       __restrict__ out) {
    int gid  = blockIdx.x * blockDim.x + threadIdx.x;
    int node = gid >> 4;
    int l    = gid & 15;
    if (node >= N_NODES) return;

    unsigned mask = 0xFFFFu << ((threadIdx.x >> 4 & 1) * 16);

    int beg = g_offsets[node];
    int end = beg + g_counts[node];

    float a0 = 0.f, a1 = 0.f, a2 = 0.f, a3 = 0.f;

    for (int base = beg; base < end; base += 16) {
        int m = min(16, end - base);
        int2 ew = (l < m) ? __ldg(&g_edges[base + l]) : make_int2(0, 0);

        int j = 0;
        for (; j + 2 <= m; j += 2) {
            int s0 = __shfl_sync(mask, ew.x, j,     16);
            int w0 = __shfl_sync(mask, ew.y, j,     16);
            int s1 = __shfl_sync(mask, ew.x, j + 1, 16);
            int w1 = __shfl_sync(mask, ew.y, j + 1, 16);
            const float* h0 = (s0 < N_USERS) ? (ue + (long long)s0 * DIM)
                                             : (ie + (long long)(s0 - N_USERS) * DIM);
            const float* h1 = (s1 < N_USERS) ? (ue + (long long)s1 * DIM)
                                             : (ie + (long long)(s1 - N_USERS) * DIM);
            float4 v0 = __ldg(((const float4*)h0) + l);
            float4 v1 = __ldg(((const float4*)h1) + l);
            float  f0 = __int_as_float(w0);
            float  f1 = __int_as_float(w1);
            a0 = fmaf(f0, v0.x, a0);  a1 = fmaf(f0, v0.y, a1);
            a2 = fmaf(f0, v0.z, a2);  a3 = fmaf(f0, v0.w, a3);
            a0 = fmaf(f1, v1.x, a0);  a1 = fmaf(f1, v1.y, a1);
            a2 = fmaf(f1, v1.z, a2);  a3 = fmaf(f1, v1.w, a3);
        }
        if (j < m) {
            int s0 = __shfl_sync(mask, ew.x, j, 16);
            int w0 = __shfl_sync(mask, ew.y, j, 16);
            const float* h0 = (s0 < N_USERS) ? (ue + (long long)s0 * DIM)
                                             : (ie + (long long)(s0 - N_USERS) * DIM);
            float4 v0 = __ldg(((const float4*)h0) + l);
            float  f0 = __int_as_float(w0);
            a0 = fmaf(f0, v0.x, a0);  a1 = fmaf(f0, v0.y, a1);
            a2 = fmaf(f0, v0.z, a2);  a3 = fmaf(f0, v0.w, a3);
        }
    }

    float ss = a0 * a0 + a1 * a1 + a2 * a2 + a3 * a3;
    #pragma unroll
    for (int off = 8; off; off >>= 1)
        ss += __shfl_xor_sync(mask, ss, off, 16);

    float scale = 1.0f / fmaxf(sqrtf(ss), EPS);
    float4 r = make_float4(a0 * scale, a1 * scale, a2 * scale, a3 * scale);
    ((float4*)(out + (long long)node * DIM))[l] = r;
}

// ---------------------------------------------------------------------------
// Launch
// ---------------------------------------------------------------------------
extern "C" void kernel_launch(void* const* d_in, const int* in_sizes, int n_in,
                              void* d_out, int out_size) {
    const float* ue  = (const float*)d_in[0];
    const float* ie  = (const float*)d_in[1];
    const int*   src = (const int*)  d_in[2];
    const int*   dst = (const int*)  d_in[3];
    const float* w   = (const float*)d_in[4];
    float*       out = (float*)d_out;

    const int E  = in_sizes[2];
    const int E4 = (E + 3) / 4;

    zero_counts_kernel<<<(N_NODES + 255) / 256, 256>>>();
    hist_kernel<<<(E4 + 255) / 256, 256>>>(dst, E);
    base_assign_kernel<<<(N_NODES + 255) / 256, 256>>>();
    scatter_pack_kernel<<<(E4 + 255) / 256, 256>>>(src, dst, w, E);

    long long nt = (long long)N_NODES * 16;
    aggregate_kernel<<<(int)((nt + 255) / 256), 256>>>(ue, ie, out);
}

// round 5
// speedup vs baseline: 1.4665x; 1.0019x over previous
#include <cuda_runtime.h>

#define N_USERS 200000
#define N_ITEMS 100000
#define N_NODES (N_USERS + N_ITEMS)
#define N_EDGES_MAX 1250000
#define DIM 64
#define EPS 1e-12f

// ---------------------------------------------------------------------------
// Scratch (device globals — no allocations allowed)
// ---------------------------------------------------------------------------
__device__ int  g_counts[N_NODES];
__device__ int  g_offsets[N_NODES];
__device__ int  g_rank[N_EDGES_MAX];   // per-edge rank among same-dst edges
__device__ int  g_total;
__device__ int2 g_edges[N_EDGES_MAX];  // {src, weight-bits} in dst-grouped order

// ---------------------------------------------------------------------------
// 1) zero histogram counters + global base counter
// ---------------------------------------------------------------------------
__global__ void zero_counts_kernel() {
    int i = blockIdx.x * blockDim.x + threadIdx.x;
    if (i < N_NODES) g_counts[i] = 0;
    if (i == 0) g_total = 0;
}

// ---------------------------------------------------------------------------
// 2) histogram of dst. The atomic RETURN VALUE is the edge's rank among
//    same-dst edges — record it so the scatter pass needs no atomics.
// ---------------------------------------------------------------------------
__global__ void hist_rank_kernel(const int* __restrict__ dst, int n_edges) {
    int i  = blockIdx.x * blockDim.x + threadIdx.x;
    int e0 = i * 4;
    if (e0 + 3 < n_edges) {
        int4 d = *(const int4*)(dst + e0);
        int r0 = atomicAdd(&g_counts[d.x], 1);
        int r1 = atomicAdd(&g_counts[d.y], 1);
        int r2 = atomicAdd(&g_counts[d.z], 1);
        int r3 = atomicAdd(&g_counts[d.w], 1);
        *(int4*)(g_rank + e0) = make_int4(r0, r1, r2, r3);
    } else {
        for (int e = e0; e < n_edges; ++e)
            g_rank[e] = atomicAdd(&g_counts[dst[e]], 1);
    }
}

// ---------------------------------------------------------------------------
// 3) per-block scan of counts; block base via one global atomicAdd.
// ---------------------------------------------------------------------------
__global__ void base_assign_kernel() {
    __shared__ int warpTot[8];
    __shared__ int blockBase;
    int t = threadIdx.x;
    int i = blockIdx.x * blockDim.x + t;
    int lane = t & 31, wid = t >> 5;

    int c = (i < N_NODES) ? g_counts[i] : 0;

    int inc = c;
    #pragma unroll
    for (int o = 1; o < 32; o <<= 1) {
        int x = __shfl_up_sync(0xffffffffu, inc, o);
        if (lane >= o) inc += x;
    }
    if (lane == 31) warpTot[wid] = inc;
    __syncthreads();
    if (wid == 0) {
        int wv = (lane < 8) ? warpTot[lane] : 0;
        #pragma unroll
        for (int o = 1; o < 8; o <<= 1) {
            int x = __shfl_up_sync(0xffffffffu, wv, o);
            if (lane >= o) wv += x;
        }
        if (lane < 8) warpTot[lane] = wv;   // inclusive warp totals
        if (lane == 7) blockBase = atomicAdd(&g_total, wv);
    }
    __syncthreads();

    int ex = ((wid > 0) ? warpTot[wid - 1] : 0) + inc - c;
    if (i < N_NODES) g_offsets[i] = blockBase + ex;
}

// ---------------------------------------------------------------------------
// 4) atomic-free scatter: pos = offsets[dst] + rank. Pure load/store.
// ---------------------------------------------------------------------------
__global__ void scatter_pack_kernel(const int*   __restrict__ src,
                                    const int*   __restrict__ dst,
                                    const float* __restrict__ w,
                                    int n_edges) {
    int i  = blockIdx.x * blockDim.x + threadIdx.x;
    int e0 = i * 4;
    if (e0 + 3 < n_edges) {
        int4   s  = *(const int4*)  (src + e0);
        int4   d  = *(const int4*)  (dst + e0);
        float4 ww = *(const float4*)(w   + e0);
        int4   r  = *(const int4*)  (g_rank + e0);
        int p0 = __ldg(&g_offsets[d.x]) + r.x;
        int p1 = __ldg(&g_offsets[d.y]) + r.y;
        int p2 = __ldg(&g_offsets[d.z]) + r.z;
        int p3 = __ldg(&g_offsets[d.w]) + r.w;
        g_edges[p0] = make_int2(s.x, __float_as_int(ww.x));
        g_edges[p1] = make_int2(s.y, __float_as_int(ww.y));
        g_edges[p2] = make_int2(s.z, __float_as_int(ww.z));
        g_edges[p3] = make_int2(s.w, __float_as_int(ww.w));
    } else {
        for (int e = e0; e < n_edges; ++e) {
            int p = __ldg(&g_offsets[dst[e]]) + g_rank[e];
            g_edges[p] = make_int2(src[e], __float_as_int(w[e]));
        }
    }
}

// ---------------------------------------------------------------------------
// 5) HALF-WARP (16 lanes, float4) per node: gather + aggregate + normalize.
// ---------------------------------------------------------------------------
__global__ void aggregate_kernel(const float* __restrict__ ue,
                                 const float* __restrict__ ie,
                                 float*       __restrict__ out) {
    int gid  = blockIdx.x * blockDim.x + threadIdx.x;
    int node = gid >> 4;
    int l    = gid & 15;
    if (node >= N_NODES) return;

    unsigned mask = 0xFFFFu << ((threadIdx.x >> 4 & 1) * 16);

    int beg = g_offsets[node];
    int end = beg + g_counts[node];

    float a0 = 0.f, a1 = 0.f, a2 = 0.f, a3 = 0.f;

    for (int base = beg; base < end; base += 16) {
        int m = min(16, end - base);
        int2 ew = (l < m) ? __ldg(&g_edges[base + l]) : make_int2(0, 0);

        int j = 0;
        for (; j + 2 <= m; j += 2) {
            int s0 = __shfl_sync(mask, ew.x, j,     16);
            int w0 = __shfl_sync(mask, ew.y, j,     16);
            int s1 = __shfl_sync(mask, ew.x, j + 1, 16);
            int w1 = __shfl_sync(mask, ew.y, j + 1, 16);
            const float* h0 = (s0 < N_USERS) ? (ue + (long long)s0 * DIM)
                                             : (ie + (long long)(s0 - N_USERS) * DIM);
            const float* h1 = (s1 < N_USERS) ? (ue + (long long)s1 * DIM)
                                             : (ie + (long long)(s1 - N_USERS) * DIM);
            float4 v0 = __ldg(((const float4*)h0) + l);
            float4 v1 = __ldg(((const float4*)h1) + l);
            float  f0 = __int_as_float(w0);
            float  f1 = __int_as_float(w1);
            a0 = fmaf(f0, v0.x, a0);  a1 = fmaf(f0, v0.y, a1);
            a2 = fmaf(f0, v0.z, a2);  a3 = fmaf(f0, v0.w, a3);
            a0 = fmaf(f1, v1.x, a0);  a1 = fmaf(f1, v1.y, a1);
            a2 = fmaf(f1, v1.z, a2);  a3 = fmaf(f1, v1.w, a3);
        }
        if (j < m) {
            int s0 = __shfl_sync(mask, ew.x, j, 16);
            int w0 = __shfl_sync(mask, ew.y, j, 16);
            const float* h0 = (s0 < N_USERS) ? (ue + (long long)s0 * DIM)
                                             : (ie + (long long)(s0 - N_USERS) * DIM);
            float4 v0 = __ldg(((const float4*)h0) + l);
            float  f0 = __int_as_float(w0);
            a0 = fmaf(f0, v0.x, a0);  a1 = fmaf(f0, v0.y, a1);
            a2 = fmaf(f0, v0.z, a2);  a3 = fmaf(f0, v0.w, a3);
        }
    }

    float ss = a0 * a0 + a1 * a1 + a2 * a2 + a3 * a3;
    #pragma unroll
    for (int off = 8; off; off >>= 1)
        ss += __shfl_xor_sync(mask, ss, off, 16);

    float scale = 1.0f / fmaxf(sqrtf(ss), EPS);
    float4 r = make_float4(a0 * scale, a1 * scale, a2 * scale, a3 * scale);
    ((float4*)(out + (long long)node * DIM))[l] = r;
}

// ---------------------------------------------------------------------------
// Launch
// ---------------------------------------------------------------------------
extern "C" void kernel_launch(void* const* d_in, const int* in_sizes, int n_in,
                              void* d_out, int out_size) {
    const float* ue  = (const float*)d_in[0];
    const float* ie  = (const float*)d_in[1];
    const int*   src = (const int*)  d_in[2];
    const int*   dst = (const int*)  d_in[3];
    const float* w   = (const float*)d_in[4];
    float*       out = (float*)d_out;

    const int E  = in_sizes[2];
    const int E4 = (E + 3) / 4;

    zero_counts_kernel<<<(N_NODES + 255) / 256, 256>>>();
    hist_rank_kernel<<<(E4 + 255) / 256, 256>>>(dst, E);
    base_assign_kernel<<<(N_NODES + 255) / 256, 256>>>();
    scatter_pack_kernel<<<(E4 + 255) / 256, 256>>>(src, dst, w, E);

    long long nt = (long long)N_NODES * 16;
    aggregate_kernel<<<(int)((nt + 255) / 256), 256>>>(ue, ie, out);
}

// round 6
// speedup vs baseline: 1.5887x; 1.0834x over previous
#include <cuda_runtime.h>

#define N_USERS 200000
#define N_ITEMS 100000
#define N_NODES (N_USERS + N_ITEMS)
#define N_EDGES_MAX 1250000
#define DIM 64
#define EPS 1e-12f

// ---------------------------------------------------------------------------
// Scratch (device globals — no allocations allowed)
// ---------------------------------------------------------------------------
__device__ int  g_counts[N_NODES];
__device__ int  g_offsets[N_NODES];
__device__ int  g_rank[N_EDGES_MAX];   // per-edge rank among same-dst edges
__device__ int  g_total;
__device__ int2 g_edges[N_EDGES_MAX];  // {src, weight-bits} in dst-grouped order

// ---------------------------------------------------------------------------
// 1) zero histogram counters + global base counter
// ---------------------------------------------------------------------------
__global__ void zero_counts_kernel() {
    int i = blockIdx.x * blockDim.x + threadIdx.x;
    if (i < N_NODES) g_counts[i] = 0;
    if (i == 0) g_total = 0;
}

// ---------------------------------------------------------------------------
// 2) histogram of dst; atomic return value = edge's rank among same-dst edges
// ---------------------------------------------------------------------------
__global__ void hist_rank_kernel(const int* __restrict__ dst, int n_edges) {
    int i  = blockIdx.x * blockDim.x + threadIdx.x;
    int e0 = i * 8;
    if (e0 + 7 < n_edges) {
        int4 d0 = *(const int4*)(dst + e0);
        int4 d1 = *(const int4*)(dst + e0 + 4);
        int r0 = atomicAdd(&g_counts[d0.x], 1);
        int r1 = atomicAdd(&g_counts[d0.y], 1);
        int r2 = atomicAdd(&g_counts[d0.z], 1);
        int r3 = atomicAdd(&g_counts[d0.w], 1);
        int r4 = atomicAdd(&g_counts[d1.x], 1);
        int r5 = atomicAdd(&g_counts[d1.y], 1);
        int r6 = atomicAdd(&g_counts[d1.z], 1);
        int r7 = atomicAdd(&g_counts[d1.w], 1);
        *(int4*)(g_rank + e0)     = make_int4(r0, r1, r2, r3);
        *(int4*)(g_rank + e0 + 4) = make_int4(r4, r5, r6, r7);
    } else {
        for (int e = e0; e < n_edges; ++e)
            g_rank[e] = atomicAdd(&g_counts[dst[e]], 1);
    }
}

// ---------------------------------------------------------------------------
// 3) per-block scan of counts; block base via one global atomicAdd.
// ---------------------------------------------------------------------------
__global__ void base_assign_kernel() {
    __shared__ int warpTot[8];
    __shared__ int blockBase;
    int t = threadIdx.x;
    int i = blockIdx.x * blockDim.x + t;
    int lane = t & 31, wid = t >> 5;

    int c = (i < N_NODES) ? g_counts[i] : 0;

    int inc = c;
    #pragma unroll
    for (int o = 1; o < 32; o <<= 1) {
        int x = __shfl_up_sync(0xffffffffu, inc, o);
        if (lane >= o) inc += x;
    }
    if (lane == 31) warpTot[wid] = inc;
    __syncthreads();
    if (wid == 0) {
        int wv = (lane < 8) ? warpTot[lane] : 0;
        #pragma unroll
        for (int o = 1; o < 8; o <<= 1) {
            int x = __shfl_up_sync(0xffffffffu, wv, o);
            if (lane >= o) wv += x;
        }
        if (lane < 8) warpTot[lane] = wv;
        if (lane == 7) blockBase = atomicAdd(&g_total, wv);
    }
    __syncthreads();

    int ex = ((wid > 0) ? warpTot[wid - 1] : 0) + inc - c;
    if (i < N_NODES) g_offsets[i] = blockBase + ex;
}

// ---------------------------------------------------------------------------
// 4) atomic-free scatter: pos = offsets[dst] + rank. 8 edges/thread.
// ---------------------------------------------------------------------------
__global__ void scatter_pack_kernel(const int*   __restrict__ src,
                                    const int*   __restrict__ dst,
                                    const float* __restrict__ w,
                                    int n_edges) {
    int i  = blockIdx.x * blockDim.x + threadIdx.x;
    int e0 = i * 8;
    if (e0 + 7 < n_edges) {
        #pragma unroll
        for (int half = 0; half < 2; ++half) {
            int b = e0 + half * 4;
            int4   s  = *(const int4*)  (src + b);
            int4   d  = *(const int4*)  (dst + b);
            float4 ww = *(const float4*)(w   + b);
            int4   r  = *(const int4*)  (g_rank + b);
            int p0 = __ldg(&g_offsets[d.x]) + r.x;
            int p1 = __ldg(&g_offsets[d.y]) + r.y;
            int p2 = __ldg(&g_offsets[d.z]) + r.z;
            int p3 = __ldg(&g_offsets[d.w]) + r.w;
            g_edges[p0] = make_int2(s.x, __float_as_int(ww.x));
            g_edges[p1] = make_int2(s.y, __float_as_int(ww.y));
            g_edges[p2] = make_int2(s.z, __float_as_int(ww.z));
            g_edges[p3] = make_int2(s.w, __float_as_int(ww.w));
        }
    } else {
        for (int e = e0; e < n_edges; ++e) {
            int p = __ldg(&g_offsets[dst[e]]) + g_rank[e];
            g_edges[p] = make_int2(src[e], __float_as_int(w[e]));
        }
    }
}

// ---------------------------------------------------------------------------
// 5) 8 LANES per node (4 nodes/warp), 2x float4 per lane:
//    gather + aggregate + L2-normalize + store. Max MLP per warp.
// ---------------------------------------------------------------------------
__global__ void aggregate_kernel(const float* __restrict__ ue,
                                 const float* __restrict__ ie,
                                 float*       __restrict__ out) {
    int gid  = blockIdx.x * blockDim.x + threadIdx.x;
    int node = gid >> 3;
    int l    = gid & 7;
    if (node >= N_NODES) return;

    unsigned mask = 0xFFu << (((threadIdx.x >> 3) & 3) * 8);

    int beg = g_offsets[node];
    int end = beg + g_counts[node];

    float a0 = 0.f, a1 = 0.f, a2 = 0.f, a3 = 0.f;
    float b0 = 0.f, b1 = 0.f, b2 = 0.f, b3 = 0.f;

    for (int base = beg; base < end; base += 8) {
        int m = min(8, end - base);
        int2 ew = (l < m) ? __ldg(&g_edges[base + l]) : make_int2(0, 0);

        int j = 0;
        for (; j + 2 <= m; j += 2) {
            int s0 = __shfl_sync(mask, ew.x, j,     8);
            int w0 = __shfl_sync(mask, ew.y, j,     8);
            int s1 = __shfl_sync(mask, ew.x, j + 1, 8);
            int w1 = __shfl_sync(mask, ew.y, j + 1, 8);
            const float4* h0 = (const float4*)((s0 < N_USERS)
                ? (ue + (long long)s0 * DIM)
                : (ie + (long long)(s0 - N_USERS) * DIM));
            const float4* h1 = (const float4*)((s1 < N_USERS)
                ? (ue + (long long)s1 * DIM)
                : (ie + (long long)(s1 - N_USERS) * DIM));
            float4 v0a = __ldg(h0 + l);
            float4 v0b = __ldg(h0 + l + 8);
            float4 v1a = __ldg(h1 + l);
            float4 v1b = __ldg(h1 + l + 8);
            float  f0 = __int_as_float(w0);
            float  f1 = __int_as_float(w1);
            a0 = fmaf(f0, v0a.x, a0);  a1 = fmaf(f0, v0a.y, a1);
            a2 = fmaf(f0, v0a.z, a2);  a3 = fmaf(f0, v0a.w, a3);
            b0 = fmaf(f0, v0b.x, b0);  b1 = fmaf(f0, v0b.y, b1);
            b2 = fmaf(f0, v0b.z, b2);  b3 = fmaf(f0, v0b.w, b3);
            a0 = fmaf(f1, v1a.x, a0);  a1 = fmaf(f1, v1a.y, a1);
            a2 = fmaf(f1, v1a.z, a2);  a3 = fmaf(f1, v1a.w, a3);
            b0 = fmaf(f1, v1b.x, b0);  b1 = fmaf(f1, v1b.y, b1);
            b2 = fmaf(f1, v1b.z, b2);  b3 = fmaf(f1, v1b.w, b3);
        }
        if (j < m) {
            int s0 = __shfl_sync(mask, ew.x, j, 8);
            int w0 = __shfl_sync(mask, ew.y, j, 8);
            const float4* h0 = (const float4*)((s0 < N_USERS)
                ? (ue + (long long)s0 * DIM)
                : (ie + (long long)(s0 - N_USERS) * DIM));
            float4 v0a = __ldg(h0 + l);
            float4 v0b = __ldg(h0 + l + 8);
            float  f0 = __int_as_float(w0);
            a0 = fmaf(f0, v0a.x, a0);  a1 = fmaf(f0, v0a.y, a1);
            a2 = fmaf(f0, v0a.z, a2);  a3 = fmaf(f0, v0a.w, a3);
            b0 = fmaf(f0, v0b.x, b0);  b1 = fmaf(f0, v0b.y, b1);
            b2 = fmaf(f0, v0b.z, b2);  b3 = fmaf(f0, v0b.w, b3);
        }
    }

    float ss = a0*a0 + a1*a1 + a2*a2 + a3*a3
             + b0*b0 + b1*b1 + b2*b2 + b3*b3;
    #pragma unroll
    for (int off = 4; off; off >>= 1)
        ss += __shfl_xor_sync(mask, ss, off, 8);

    float scale = 1.0f / fmaxf(sqrtf(ss), EPS);
    float4* orow = (float4*)(out + (long long)node * DIM);
    orow[l]     = make_float4(a0 * scale, a1 * scale, a2 * scale, a3 * scale);
    orow[l + 8] = make_float4(b0 * scale, b1 * scale, b2 * scale, b3 * scale);
}

// ---------------------------------------------------------------------------
// Launch
// ---------------------------------------------------------------------------
extern "C" void kernel_launch(void* const* d_in, const int* in_sizes, int n_in,
                              void* d_out, int out_size) {
    const float* ue  = (const float*)d_in[0];
    const float* ie  = (const float*)d_in[1];
    const int*   src = (const int*)  d_in[2];
    const int*   dst = (const int*)  d_in[3];
    const float* w   = (const float*)d_in[4];
    float*       out = (float*)d_out;

    const int E  = in_sizes[2];
    const int E8 = (E + 7) / 8;

    zero_counts_kernel<<<(N_NODES + 255) / 256, 256>>>();
    hist_rank_kernel<<<(E8 + 255) / 256, 256>>>(dst, E);
    base_assign_kernel<<<(N_NODES + 255) / 256, 256>>>();
    scatter_pack_kernel<<<(E8 + 255) / 256, 256>>>(src, dst, w, E);

    long long nt = (long long)N_NODES * 8;
    aggregate_kernel<<<(int)((nt + 255) / 256), 256>>>(ue, ie, out);
}